// round 2
// baseline (speedup 1.0000x reference)
#include <cuda_runtime.h>
#include <math.h>

#define NTOKEN 50257
#define NROWS  2240
#define DIM    400

#define BM 128
#define BN 128
#define BK 16

// Scratch (no allocations allowed in kernel_launch)
__device__ int   g_last[NTOKEN];
__device__ float g_sfac[NROWS];
__device__ float g_noise[NROWS];
__device__ float g_lse[NROWS];

__global__ void k_init_last(const int* __restrict__ tgt) {
    int i = blockIdx.x * blockDim.x + threadIdx.x;
    if (i < NROWS) g_last[tgt[i]] = -1;   // only touch used tokens
}

__device__ __forceinline__ float warp_sum(float v) {
    #pragma unroll
    for (int o = 16; o; o >>= 1) v += __shfl_down_sync(0xffffffffu, v, o);
    return v;
}

// Per-row: n_output, n_w, cos indicator -> scale factor s_i so that
// noise_row_i = s_i * h_i ;  also record last-writer index per target token.
__global__ void k_row_stats(const float* __restrict__ h,
                            const float* __restrict__ enc_w,
                            const int* __restrict__ tgt) {
    int row = blockIdx.x;
    int t = tgt[row];
    const float* hr = h + (long long)row * DIM;
    const float* wr = enc_w + (long long)t * DIM;
    float hsq = 0.f, dhw = 0.f, wsq = 0.f;
    for (int k = threadIdx.x; k < DIM; k += blockDim.x) {
        float hv = hr[k], wv = wr[k];
        hsq += hv * hv;
        dhw += hv * wv;
        wsq += wv * wv;
    }
    __shared__ float sh[3][4];
    int lane = threadIdx.x & 31, w = threadIdx.x >> 5;
    hsq = warp_sum(hsq); dhw = warp_sum(dhw); wsq = warp_sum(wsq);
    if (lane == 0) { sh[0][w] = hsq; sh[1][w] = dhw; sh[2][w] = wsq; }
    __syncthreads();
    if (threadIdx.x == 0) {
        hsq = sh[0][0] + sh[0][1] + sh[0][2] + sh[0][3];
        dhw = sh[1][0] + sh[1][1] + sh[1][2] + sh[1][3];
        wsq = sh[2][0] + sh[2][1] + sh[2][2] + sh[2][3];
        float n_out = sqrtf(hsq + 1e-8f);
        float n_w   = sqrtf(wsq + 1e-8f);
        float cosv  = dhw / (n_out * n_w);
        float eps   = (cosv > 0.f) ? 0.2f * n_w : 0.f;
        g_sfac[row] = -eps / n_out;              // noise_row = sfac * h_row
        atomicMax(&g_last[t], row);              // last write wins on dups
    }
}

// noise_outputs[i] = h_i . (sfac[j] * h_j), j = last[target_i]
__global__ void k_noise(const float* __restrict__ h,
                        const int* __restrict__ tgt) {
    int row = blockIdx.x;
    int j = g_last[tgt[row]];
    const float* hi = h + (long long)row * DIM;
    const float* hj = h + (long long)j * DIM;
    float d = 0.f;
    for (int k = threadIdx.x; k < DIM; k += blockDim.x) d += hi[k] * hj[k];
    __shared__ float sh[4];
    d = warp_sum(d);
    if ((threadIdx.x & 31) == 0) sh[threadIdx.x >> 5] = d;
    __syncthreads();
    if (threadIdx.x == 0)
        g_noise[row] = g_sfac[j] * (sh[0] + sh[1] + sh[2] + sh[3]);
}

// Tiled fp32 GEMM: out[i,c] = h_i . dec_w_c + dec_b[c] (+ noise on target col)
__global__ void __launch_bounds__(256) k_gemm(
    const float* __restrict__ A, const float* __restrict__ B,
    const float* __restrict__ bias, const int* __restrict__ tgt,
    float* __restrict__ out)
{
    __shared__ float As[BK][BM];
    __shared__ float Bs[BK][BN];
    int tid = threadIdx.x;
    int rowBase = blockIdx.y * BM;
    int colBase = blockIdx.x * BN;
    int tr = tid >> 4;   // 0..15
    int tc = tid & 15;   // 0..15

    float acc[8][8];
    #pragma unroll
    for (int m = 0; m < 8; m++)
        #pragma unroll
        for (int n = 0; n < 8; n++) acc[m][n] = 0.f;

    for (int kt = 0; kt < DIM; kt += BK) {
        // Load A tile: 128 rows x 16 k (as 512 float4, 2 per thread), transposed to As[k][row]
        #pragma unroll
        for (int i = 0; i < 2; i++) {
            int idx = tid + i * 256;
            int r   = idx >> 2;
            int k4  = (idx & 3) << 2;
            float4 v = make_float4(0.f, 0.f, 0.f, 0.f);
            int gr = rowBase + r;
            if (gr < NROWS)
                v = *reinterpret_cast<const float4*>(A + (long long)gr * DIM + kt + k4);
            As[k4 + 0][r] = v.x; As[k4 + 1][r] = v.y;
            As[k4 + 2][r] = v.z; As[k4 + 3][r] = v.w;
        }
        // Load B tile: 128 cols x 16 k, transposed to Bs[k][col]
        #pragma unroll
        for (int i = 0; i < 2; i++) {
            int idx = tid + i * 256;
            int c   = idx >> 2;
            int k4  = (idx & 3) << 2;
            float4 v = make_float4(0.f, 0.f, 0.f, 0.f);
            int gc = colBase + c;
            if (gc < NTOKEN)
                v = *reinterpret_cast<const float4*>(B + (long long)gc * DIM + kt + k4);
            Bs[k4 + 0][c] = v.x; Bs[k4 + 1][c] = v.y;
            Bs[k4 + 2][c] = v.z; Bs[k4 + 3][c] = v.w;
        }
        __syncthreads();

        #pragma unroll
        for (int kk = 0; kk < BK; kk++) {
            float a[8], b[8];
            #pragma unroll
            for (int m = 0; m < 4; m++) {
                a[m]     = As[kk][tr * 4 + m];
                a[m + 4] = As[kk][64 + tr * 4 + m];
            }
            #pragma unroll
            for (int n = 0; n < 4; n++) {
                b[n]     = Bs[kk][tc * 4 + n];
                b[n + 4] = Bs[kk][64 + tc * 4 + n];
            }
            #pragma unroll
            for (int m = 0; m < 8; m++)
                #pragma unroll
                for (int n = 0; n < 8; n++)
                    acc[m][n] = fmaf(a[m], b[n], acc[m][n]);
        }
        __syncthreads();
    }

    // Epilogue: bias + target-column noise, write logits
    #pragma unroll
    for (int m = 0; m < 8; m++) {
        int gr = rowBase + ((m < 4) ? tr * 4 + m : 64 + tr * 4 + (m - 4));
        if (gr >= NROWS) continue;
        int t = tgt[gr];
        float nz = g_noise[gr];
        long long rb = (long long)gr * NTOKEN;
        #pragma unroll
        for (int n = 0; n < 8; n++) {
            int gc = colBase + ((n < 4) ? tc * 4 + n : 64 + tc * 4 + (n - 4));
            if (gc >= NTOKEN) continue;
            float v = acc[m][n] + bias[gc];
            if (gc == t) v += nz;
            out[rb + gc] = v;
        }
    }
}

// Per-row online logsumexp
__global__ void k_lse(const float* __restrict__ out) {
    int row = blockIdx.x;
    const float* p = out + (long long)row * NTOKEN;
    float m = -1e30f, s = 0.f;
    for (int c = threadIdx.x; c < NTOKEN; c += blockDim.x) {
        float v = p[c];
        if (v > m) { s = s * expf(m - v) + 1.f; m = v; }
        else       { s += expf(v - m); }
    }
    __shared__ float sm[256], ss[256];
    sm[threadIdx.x] = m; ss[threadIdx.x] = s;
    __syncthreads();
    for (int o = 128; o; o >>= 1) {
        if (threadIdx.x < o) {
            float m1 = sm[threadIdx.x],     s1 = ss[threadIdx.x];
            float m2 = sm[threadIdx.x + o], s2 = ss[threadIdx.x + o];
            float mm = fmaxf(m1, m2);
            sm[threadIdx.x] = mm;
            ss[threadIdx.x] = s1 * expf(m1 - mm) + s2 * expf(m2 - mm);
        }
        __syncthreads();
    }
    if (threadIdx.x == 0) g_lse[row] = sm[0] + logf(ss[0]);
}

// In-place: logits -> log_softmax
__global__ void k_sub(float* __restrict__ out) {
    int row = blockIdx.x;
    float l = g_lse[row];
    float* p = out + (long long)row * NTOKEN;
    for (int c = threadIdx.x; c < NTOKEN; c += blockDim.x) p[c] -= l;
}

extern "C" void kernel_launch(void* const* d_in, const int* in_sizes, int n_in,
                              void* d_out, int out_size) {
    const float* x     = (const float*)d_in[0];
    const float* dec_w = (const float*)d_in[1];
    const float* dec_b = (const float*)d_in[2];
    const float* enc_w = (const float*)d_in[3];
    const int*   tgt   = (const int*)d_in[4];   // JAX w/o x64 downcasts int64->int32
    float* out = (float*)d_out;

    k_init_last<<<(NROWS + 255) / 256, 256>>>(tgt);
    k_row_stats<<<NROWS, 128>>>(x, enc_w, tgt);
    k_noise<<<NROWS, 128>>>(x, tgt);

    dim3 grid((NTOKEN + BN - 1) / BN, (NROWS + BM - 1) / BM);
    k_gemm<<<grid, 256>>>(x, dec_w, dec_b, tgt, out);

    k_lse<<<NROWS, 256>>>(out);
    k_sub<<<NROWS, 256>>>(out);
}

// round 5
// speedup vs baseline: 3.7678x; 3.7678x over previous
#include <cuda_runtime.h>
#include <cuda_bf16.h>
#include <stdint.h>
#include <math.h>

#define NTOKEN 50257
#define NROWS  2240
#define DIM    400
#define KPAD   416              // 13 * 32
#define MPAD   2304             // 18 * 128
#define NPAD   50304            // 393 * 128
#define KTILES 13
#define SSTRIDE 40              // bf16 elems per smem row (80B) -> conflict-free ldmatrix

// ---------------- device scratch ----------------
__device__ int   g_last[NTOKEN];
__device__ float g_sfac[NROWS];
__device__ float g_noise[NROWS];
__device__ float g_lse[NROWS];
__device__ __nv_bfloat16 g_xa[(size_t)MPAD * KPAD];
__device__ __nv_bfloat16 g_wb[(size_t)NPAD * KPAD];

// ---------------- helpers ----------------
__device__ __forceinline__ uint32_t smem_u32(const void* p) {
    uint32_t a;
    asm("{ .reg .u64 t; cvta.to.shared.u64 t, %1; cvt.u32.u64 %0, t; }" : "=r"(a) : "l"(p));
    return a;
}
__device__ __forceinline__ void ldsm_x4(uint32_t& r0, uint32_t& r1, uint32_t& r2, uint32_t& r3,
                                        uint32_t addr) {
    asm volatile("ldmatrix.sync.aligned.m8n8.x4.shared.b16 {%0,%1,%2,%3}, [%4];"
                 : "=r"(r0), "=r"(r1), "=r"(r2), "=r"(r3) : "r"(addr));
}
__device__ __forceinline__ void mma16816(float* c, uint32_t a0, uint32_t a1, uint32_t a2,
                                         uint32_t a3, uint32_t b0, uint32_t b1) {
    asm volatile("mma.sync.aligned.m16n8k16.row.col.f32.bf16.bf16.f32 "
                 "{%0,%1,%2,%3}, {%4,%5,%6,%7}, {%8,%9}, {%0,%1,%2,%3};"
                 : "+f"(c[0]), "+f"(c[1]), "+f"(c[2]), "+f"(c[3])
                 : "r"(a0), "r"(a1), "r"(a2), "r"(a3), "r"(b0), "r"(b1));
}
__device__ __forceinline__ float warp_sum(float v) {
    #pragma unroll
    for (int o = 16; o; o >>= 1) v += __shfl_down_sync(0xffffffffu, v, o);
    return v;
}

// ---------------- prologue: fp32 -> padded bf16 scratch ----------------
__device__ __forceinline__ void cvt_body(const float* __restrict__ src,
                                         __nv_bfloat16* __restrict__ dst,
                                         int srows, long long total) {
    long long i = (long long)blockIdx.x * blockDim.x + threadIdx.x;
    if (i >= total) return;
    int row = (int)(i / (KPAD / 8));
    int g   = (int)(i % (KPAD / 8));
    __align__(16) __nv_bfloat16 v[8];
    if (row < srows && g * 8 < DIM) {
        const float* s = src + (long long)row * DIM + g * 8;
        #pragma unroll
        for (int j = 0; j < 8; j++) v[j] = __float2bfloat16(s[j]);
    } else {
        #pragma unroll
        for (int j = 0; j < 8; j++) v[j] = __float2bfloat16(0.f);
    }
    *reinterpret_cast<uint4*>(dst + (size_t)row * KPAD + g * 8) =
        *reinterpret_cast<const uint4*>(v);
}
__global__ void k_cvt_x(const float* __restrict__ src) {
    cvt_body(src, g_xa, NROWS, (long long)MPAD * (KPAD / 8));
}
__global__ void k_cvt_w(const float* __restrict__ src) {
    cvt_body(src, g_wb, NTOKEN, (long long)NPAD * (KPAD / 8));
}

// ---------------- adversarial-noise prologue ----------------
__global__ void k_init_last(const int* __restrict__ tgt) {
    int i = blockIdx.x * blockDim.x + threadIdx.x;
    if (i < NROWS) g_last[tgt[i]] = -1;
}
__global__ void k_row_stats(const float* __restrict__ h,
                            const float* __restrict__ enc_w,
                            const int* __restrict__ tgt) {
    int row = blockIdx.x;
    int t = tgt[row];
    const float* hr = h + (long long)row * DIM;
    const float* wr = enc_w + (long long)t * DIM;
    float hsq = 0.f, dhw = 0.f, wsq = 0.f;
    for (int k = threadIdx.x; k < DIM; k += blockDim.x) {
        float hv = hr[k], wv = wr[k];
        hsq += hv * hv; dhw += hv * wv; wsq += wv * wv;
    }
    __shared__ float sh[3][4];
    int lane = threadIdx.x & 31, w = threadIdx.x >> 5;
    hsq = warp_sum(hsq); dhw = warp_sum(dhw); wsq = warp_sum(wsq);
    if (lane == 0) { sh[0][w] = hsq; sh[1][w] = dhw; sh[2][w] = wsq; }
    __syncthreads();
    if (threadIdx.x == 0) {
        hsq = sh[0][0] + sh[0][1] + sh[0][2] + sh[0][3];
        dhw = sh[1][0] + sh[1][1] + sh[1][2] + sh[1][3];
        wsq = sh[2][0] + sh[2][1] + sh[2][2] + sh[2][3];
        float n_out = sqrtf(hsq + 1e-8f);
        float n_w   = sqrtf(wsq + 1e-8f);
        float cosv  = dhw / (n_out * n_w);
        float eps   = (cosv > 0.f) ? 0.2f * n_w : 0.f;
        g_sfac[row] = -eps / n_out;
        atomicMax(&g_last[t], row);
    }
}
__global__ void k_noise(const float* __restrict__ h, const int* __restrict__ tgt) {
    int row = blockIdx.x;
    int j = g_last[tgt[row]];
    const float* hi = h + (long long)row * DIM;
    const float* hj = h + (long long)j * DIM;
    float d = 0.f;
    for (int k = threadIdx.x; k < DIM; k += blockDim.x) d += hi[k] * hj[k];
    __shared__ float sh[4];
    d = warp_sum(d);
    if ((threadIdx.x & 31) == 0) sh[threadIdx.x >> 5] = d;
    __syncthreads();
    if (threadIdx.x == 0)
        g_noise[row] = g_sfac[j] * (sh[0] + sh[1] + sh[2] + sh[3]);
}

// ---------------- HMMA bf16 GEMM (mma.sync) with fused epilogue ----------------
// 128x128 tile, K=416 in 13 chunks of 32, double-buffered SMEM, 8 warps (4M x 2N),
// per-warp 32x64 = 2 m16 x 8 n8 fragments.
__global__ void __launch_bounds__(256, 2) k_gemm_tc(
    const float* __restrict__ bias, const int* __restrict__ tgt,
    float* __restrict__ out)
{
    __shared__ __align__(16) __nv_bfloat16 sA[2][128 * SSTRIDE];
    __shared__ __align__(16) __nv_bfloat16 sB[2][128 * SSTRIDE];
    __shared__ int   s_tgt[128];
    __shared__ float s_noise[128];
    __shared__ float s_bias[128];

    int tid = threadIdx.x, lane = tid & 31, wid = tid >> 5;
    int warpM = wid & 3, warpN = wid >> 2;
    int rowBase = blockIdx.y * 128, colBase = blockIdx.x * 128;

    if (tid < 128) {
        int gr = rowBase + tid;
        s_tgt[tid]   = (gr < NROWS) ? tgt[gr]     : -1;
        s_noise[tid] = (gr < NROWS) ? g_noise[gr] : 0.f;
        int gc = colBase + tid;
        s_bias[tid]  = (gc < NTOKEN) ? bias[gc]   : 0.f;
    }

    // global->reg load indices (512 16B chunks per tile per matrix; 2 per thread)
    int i0 = tid, i1 = tid + 256;
    int r0 = i0 >> 2, c0 = (i0 & 3) * 8;
    int r1 = i1 >> 2, c1 = (i1 & 3) * 8;

    float acc[2][8][4];
    #pragma unroll
    for (int m = 0; m < 2; m++)
        #pragma unroll
        for (int n = 0; n < 8; n++)
            #pragma unroll
            for (int j = 0; j < 4; j++) acc[m][n][j] = 0.f;

    uint4 ra0, ra1, rb0, rb1;
    // preload tile 0
    {
        ra0 = *(const uint4*)&g_xa[(size_t)(rowBase + r0) * KPAD + c0];
        ra1 = *(const uint4*)&g_xa[(size_t)(rowBase + r1) * KPAD + c1];
        rb0 = *(const uint4*)&g_wb[(size_t)(colBase + r0) * KPAD + c0];
        rb1 = *(const uint4*)&g_wb[(size_t)(colBase + r1) * KPAD + c1];
        *(uint4*)&sA[0][r0 * SSTRIDE + c0] = ra0;
        *(uint4*)&sA[0][r1 * SSTRIDE + c1] = ra1;
        *(uint4*)&sB[0][r0 * SSTRIDE + c0] = rb0;
        *(uint4*)&sB[0][r1 * SSTRIDE + c1] = rb1;
    }
    __syncthreads();

    for (int kt = 0; kt < KTILES; kt++) {
        int buf = kt & 1;
        if (kt + 1 < KTILES) {
            int k0 = (kt + 1) * 32;
            ra0 = *(const uint4*)&g_xa[(size_t)(rowBase + r0) * KPAD + k0 + c0];
            ra1 = *(const uint4*)&g_xa[(size_t)(rowBase + r1) * KPAD + k0 + c1];
            rb0 = *(const uint4*)&g_wb[(size_t)(colBase + r0) * KPAD + k0 + c0];
            rb1 = *(const uint4*)&g_wb[(size_t)(colBase + r1) * KPAD + k0 + c1];
        }
        uint32_t aBase = smem_u32(sA[buf]);
        uint32_t bBase = smem_u32(sB[buf]);
        #pragma unroll
        for (int s = 0; s < 2; s++) {
            uint32_t a[2][4];
            #pragma unroll
            for (int mf = 0; mf < 2; mf++) {
                int row = warpM * 32 + mf * 16 + (lane & 7) + ((lane >> 3) & 1) * 8;
                uint32_t addr = aBase + row * 80 + s * 32 + ((lane >> 4) & 1) * 16;
                ldsm_x4(a[mf][0], a[mf][1], a[mf][2], a[mf][3], addr);
            }
            uint32_t b[8][2];
            #pragma unroll
            for (int nf2 = 0; nf2 < 4; nf2++) {
                int rn = warpN * 64 + nf2 * 16 + (lane & 7) + ((lane >> 4) & 1) * 8;
                uint32_t addr = bBase + rn * 80 + s * 32 + ((lane >> 3) & 1) * 16;
                ldsm_x4(b[nf2 * 2][0], b[nf2 * 2][1], b[nf2 * 2 + 1][0], b[nf2 * 2 + 1][1], addr);
            }
            #pragma unroll
            for (int mf = 0; mf < 2; mf++)
                #pragma unroll
                for (int nf = 0; nf < 8; nf++)
                    mma16816(acc[mf][nf], a[mf][0], a[mf][1], a[mf][2], a[mf][3],
                             b[nf][0], b[nf][1]);
        }
        if (kt + 1 < KTILES) {
            int nb = buf ^ 1;
            *(uint4*)&sA[nb][r0 * SSTRIDE + c0] = ra0;
            *(uint4*)&sA[nb][r1 * SSTRIDE + c1] = ra1;
            *(uint4*)&sB[nb][r0 * SSTRIDE + c0] = rb0;
            *(uint4*)&sB[nb][r1 * SSTRIDE + c1] = rb1;
        }
        __syncthreads();
    }

    // Register epilogue: bias + target-column noise. Scalar stores only:
    // out rows are NOT 8B-aligned (NTOKEN odd), float2 would trap on odd rows.
    int groupRow = lane >> 2;
    int colPair  = (lane & 3) * 2;
    #pragma unroll
    for (int mf = 0; mf < 2; mf++) {
        #pragma unroll
        for (int half = 0; half < 2; half++) {
            int rl = warpM * 32 + mf * 16 + groupRow + half * 8;
            int gr = rowBase + rl;
            if (gr >= NROWS) continue;
            int t = s_tgt[rl];
            float nz = s_noise[rl];
            size_t ob = (size_t)gr * NTOKEN;
            #pragma unroll
            for (int nf = 0; nf < 8; nf++) {
                int cl = warpN * 64 + nf * 8 + colPair;
                int gc = colBase + cl;
                float v0 = acc[mf][nf][half * 2 + 0] + s_bias[cl];
                float v1 = acc[mf][nf][half * 2 + 1] + s_bias[cl + 1];
                if (gc == t)     v0 += nz;
                if (gc + 1 == t) v1 += nz;
                if (gc < NTOKEN)     out[ob + gc]     = v0;
                if (gc + 1 < NTOKEN) out[ob + gc + 1] = v1;
            }
        }
    }
}

// ---------------- softmax passes (alignment-safe: NTOKEN odd!) ----------------
__global__ void k_lse(const float* __restrict__ out) {
    int row = blockIdx.x;
    const float* p = out + (size_t)row * NTOKEN;
    // head: elements until p+head is 16B aligned
    int head = (int)(((16u - ((uint32_t)(uintptr_t)p & 15u)) & 15u) >> 2);
    int n4 = (NTOKEN - head) >> 2;
    int tail = NTOKEN - head - n4 * 4;

    float m = -1e30f, s = 0.f;
    if (threadIdx.x < (unsigned)head) {
        float v = p[threadIdx.x];
        m = v; s = 1.f;
    }
    const float4* p4 = (const float4*)(p + head);
    for (int i = threadIdx.x; i < n4; i += blockDim.x) {
        float4 v = p4[i];
        float mx = fmaxf(fmaxf(v.x, v.y), fmaxf(v.z, v.w));
        if (mx > m) { s *= __expf(m - mx); m = mx; }
        s += __expf(v.x - m) + __expf(v.y - m) + __expf(v.z - m) + __expf(v.w - m);
    }
    if (threadIdx.x < (unsigned)tail) {
        float v = p[head + n4 * 4 + threadIdx.x];
        if (v > m) { s *= __expf(m - v); m = v; }
        s += __expf(v - m);
    }
    __shared__ float sm[512], ss[512];
    sm[threadIdx.x] = m; ss[threadIdx.x] = s;
    __syncthreads();
    for (int o = 256; o; o >>= 1) {
        if (threadIdx.x < o) {
            float m1 = sm[threadIdx.x],     s1 = ss[threadIdx.x];
            float m2 = sm[threadIdx.x + o], s2 = ss[threadIdx.x + o];
            float mm = fmaxf(m1, m2);
            sm[threadIdx.x] = mm;
            ss[threadIdx.x] = s1 * __expf(m1 - mm) + s2 * __expf(m2 - mm);
        }
        __syncthreads();
    }
    if (threadIdx.x == 0) g_lse[row] = sm[0] + __logf(ss[0]);
}

__global__ void k_sub(float* __restrict__ out) {
    int row = blockIdx.x;
    float l = g_lse[row];
    float* p = out + (size_t)row * NTOKEN;
    int head = (int)(((16u - ((uint32_t)(uintptr_t)p & 15u)) & 15u) >> 2);
    int n4 = (NTOKEN - head) >> 2;
    int tail = NTOKEN - head - n4 * 4;

    if (threadIdx.x < (unsigned)head) p[threadIdx.x] -= l;
    float4* p4 = (float4*)(p + head);
    for (int i = threadIdx.x; i < n4; i += blockDim.x) {
        float4 v = p4[i];
        v.x -= l; v.y -= l; v.z -= l; v.w -= l;
        p4[i] = v;
    }
    if (threadIdx.x < (unsigned)tail) p[head + n4 * 4 + threadIdx.x] -= l;
}

// ---------------- launch ----------------
extern "C" void kernel_launch(void* const* d_in, const int* in_sizes, int n_in,
                              void* d_out, int out_size) {
    const float* x     = (const float*)d_in[0];
    const float* dec_w = (const float*)d_in[1];
    const float* dec_b = (const float*)d_in[2];
    const float* enc_w = (const float*)d_in[3];
    const int*   tgt   = (const int*)d_in[4];
    float* out = (float*)d_out;

    long long xg = (long long)MPAD * (KPAD / 8);
    long long wg = (long long)NPAD * (KPAD / 8);
    k_cvt_x<<<(unsigned)((xg + 255) / 256), 256>>>(x);
    k_cvt_w<<<(unsigned)((wg + 255) / 256), 256>>>(dec_w);

    k_init_last<<<(NROWS + 255) / 256, 256>>>(tgt);
    k_row_stats<<<NROWS, 128>>>(x, enc_w, tgt);
    k_noise<<<NROWS, 128>>>(x, tgt);

    dim3 grid(NPAD / 128, MPAD / 128);
    k_gemm_tc<<<grid, 256>>>(dec_b, tgt, out);

    k_lse<<<NROWS, 512>>>(out);
    k_sub<<<NROWS, 1024>>>(out);
}

// round 6
// speedup vs baseline: 4.0811x; 1.0831x over previous
#include <cuda_runtime.h>
#include <cuda_bf16.h>
#include <stdint.h>
#include <math.h>

#define NTOKEN 50257
#define NROWS  2240
#define DIM    400
#define KPAD   416              // 13 * 32
#define MPAD   2304             // 18 * 128
#define NPAD   50304            // 393 * 128
#define KTILES 13
#define NTILES (NPAD / 128)     // 393 col-tiles
#define SSTRIDE 40              // bf16 elems per smem row (80B) -> conflict-free ldmatrix

// ---------------- device scratch ----------------
__device__ int   g_last[NTOKEN];
__device__ float g_sfac[NROWS];
__device__ float g_noise[NROWS];
__device__ float g_lse[NROWS];
__device__ float g_pm[(size_t)NROWS * NTILES];
__device__ float g_ps[(size_t)NROWS * NTILES];
__device__ __nv_bfloat16 g_xa[(size_t)MPAD * KPAD];
__device__ __nv_bfloat16 g_wb[(size_t)NPAD * KPAD];

// ---------------- helpers ----------------
__device__ __forceinline__ uint32_t smem_u32(const void* p) {
    uint32_t a;
    asm("{ .reg .u64 t; cvta.to.shared.u64 t, %1; cvt.u32.u64 %0, t; }" : "=r"(a) : "l"(p));
    return a;
}
__device__ __forceinline__ void ldsm_x4(uint32_t& r0, uint32_t& r1, uint32_t& r2, uint32_t& r3,
                                        uint32_t addr) {
    asm volatile("ldmatrix.sync.aligned.m8n8.x4.shared.b16 {%0,%1,%2,%3}, [%4];"
                 : "=r"(r0), "=r"(r1), "=r"(r2), "=r"(r3) : "r"(addr));
}
__device__ __forceinline__ void mma16816(float* c, uint32_t a0, uint32_t a1, uint32_t a2,
                                         uint32_t a3, uint32_t b0, uint32_t b1) {
    asm volatile("mma.sync.aligned.m16n8k16.row.col.f32.bf16.bf16.f32 "
                 "{%0,%1,%2,%3}, {%4,%5,%6,%7}, {%8,%9}, {%0,%1,%2,%3};"
                 : "+f"(c[0]), "+f"(c[1]), "+f"(c[2]), "+f"(c[3])
                 : "r"(a0), "r"(a1), "r"(a2), "r"(a3), "r"(b0), "r"(b1));
}
__device__ __forceinline__ float warp_sum(float v) {
    #pragma unroll
    for (int o = 16; o; o >>= 1) v += __shfl_down_sync(0xffffffffu, v, o);
    return v;
}

// ---------------- prologue: fp32 -> padded bf16 scratch ----------------
__device__ __forceinline__ void cvt_body(const float* __restrict__ src,
                                         __nv_bfloat16* __restrict__ dst,
                                         int srows, long long total) {
    long long i = (long long)blockIdx.x * blockDim.x + threadIdx.x;
    if (i >= total) return;
    int row = (int)(i / (KPAD / 8));
    int g   = (int)(i % (KPAD / 8));
    __align__(16) __nv_bfloat16 v[8];
    if (row < srows && g * 8 < DIM) {
        const float* s = src + (long long)row * DIM + g * 8;
        #pragma unroll
        for (int j = 0; j < 8; j++) v[j] = __float2bfloat16(s[j]);
    } else {
        #pragma unroll
        for (int j = 0; j < 8; j++) v[j] = __float2bfloat16(0.f);
    }
    *reinterpret_cast<uint4*>(dst + (size_t)row * KPAD + g * 8) =
        *reinterpret_cast<const uint4*>(v);
}
__global__ void k_cvt_x(const float* __restrict__ src) {
    cvt_body(src, g_xa, NROWS, (long long)MPAD * (KPAD / 8));
}
__global__ void k_cvt_w(const float* __restrict__ src) {
    cvt_body(src, g_wb, NTOKEN, (long long)NPAD * (KPAD / 8));
}

// ---------------- adversarial-noise prologue ----------------
__global__ void k_init_last(const int* __restrict__ tgt) {
    int i = blockIdx.x * blockDim.x + threadIdx.x;
    if (i < NROWS) g_last[tgt[i]] = -1;
}
__global__ void k_row_stats(const float* __restrict__ h,
                            const float* __restrict__ enc_w,
                            const int* __restrict__ tgt) {
    int row = blockIdx.x;
    int t = tgt[row];
    const float* hr = h + (long long)row * DIM;
    const float* wr = enc_w + (long long)t * DIM;
    float hsq = 0.f, dhw = 0.f, wsq = 0.f;
    for (int k = threadIdx.x; k < DIM; k += blockDim.x) {
        float hv = hr[k], wv = wr[k];
        hsq += hv * hv; dhw += hv * wv; wsq += wv * wv;
    }
    __shared__ float sh[3][4];
    int lane = threadIdx.x & 31, w = threadIdx.x >> 5;
    hsq = warp_sum(hsq); dhw = warp_sum(dhw); wsq = warp_sum(wsq);
    if (lane == 0) { sh[0][w] = hsq; sh[1][w] = dhw; sh[2][w] = wsq; }
    __syncthreads();
    if (threadIdx.x == 0) {
        hsq = sh[0][0] + sh[0][1] + sh[0][2] + sh[0][3];
        dhw = sh[1][0] + sh[1][1] + sh[1][2] + sh[1][3];
        wsq = sh[2][0] + sh[2][1] + sh[2][2] + sh[2][3];
        float n_out = sqrtf(hsq + 1e-8f);
        float n_w   = sqrtf(wsq + 1e-8f);
        float cosv  = dhw / (n_out * n_w);
        float eps   = (cosv > 0.f) ? 0.2f * n_w : 0.f;
        g_sfac[row] = -eps / n_out;
        atomicMax(&g_last[t], row);
    }
}
__global__ void k_noise(const float* __restrict__ h, const int* __restrict__ tgt) {
    int row = blockIdx.x;
    int j = g_last[tgt[row]];
    const float* hi = h + (long long)row * DIM;
    const float* hj = h + (long long)j * DIM;
    float d = 0.f;
    for (int k = threadIdx.x; k < DIM; k += blockDim.x) d += hi[k] * hj[k];
    __shared__ float sh[4];
    d = warp_sum(d);
    if ((threadIdx.x & 31) == 0) sh[threadIdx.x >> 5] = d;
    __syncthreads();
    if (threadIdx.x == 0)
        g_noise[row] = g_sfac[j] * (sh[0] + sh[1] + sh[2] + sh[3]);
}

// ---------------- HMMA bf16 GEMM + fused bias/noise + partial softmax ----------------
__global__ void __launch_bounds__(256, 2) k_gemm_tc(
    const float* __restrict__ bias, const int* __restrict__ tgt,
    float* __restrict__ out)
{
    __shared__ __align__(16) __nv_bfloat16 sA[2][128 * SSTRIDE];
    __shared__ __align__(16) __nv_bfloat16 sB[2][128 * SSTRIDE];
    __shared__ int   s_tgt[128];
    __shared__ float s_noise[128];
    __shared__ float s_bias[128];
    __shared__ float sm_m[2][128];
    __shared__ float sm_s[2][128];

    int tid = threadIdx.x, lane = tid & 31, wid = tid >> 5;
    int warpM = wid & 3, warpN = wid >> 2;
    int rowBase = blockIdx.y * 128, colBase = blockIdx.x * 128;

    if (tid < 128) {
        int gr = rowBase + tid;
        s_tgt[tid]   = (gr < NROWS) ? tgt[gr]     : -1;
        s_noise[tid] = (gr < NROWS) ? g_noise[gr] : 0.f;
        int gc = colBase + tid;
        s_bias[tid]  = (gc < NTOKEN) ? bias[gc]   : 0.f;
    }

    int i0 = tid, i1 = tid + 256;
    int r0 = i0 >> 2, c0 = (i0 & 3) * 8;
    int r1 = i1 >> 2, c1 = (i1 & 3) * 8;

    float acc[2][8][4];
    #pragma unroll
    for (int m = 0; m < 2; m++)
        #pragma unroll
        for (int n = 0; n < 8; n++)
            #pragma unroll
            for (int j = 0; j < 4; j++) acc[m][n][j] = 0.f;

    uint4 ra0, ra1, rb0, rb1;
    {
        ra0 = *(const uint4*)&g_xa[(size_t)(rowBase + r0) * KPAD + c0];
        ra1 = *(const uint4*)&g_xa[(size_t)(rowBase + r1) * KPAD + c1];
        rb0 = *(const uint4*)&g_wb[(size_t)(colBase + r0) * KPAD + c0];
        rb1 = *(const uint4*)&g_wb[(size_t)(colBase + r1) * KPAD + c1];
        *(uint4*)&sA[0][r0 * SSTRIDE + c0] = ra0;
        *(uint4*)&sA[0][r1 * SSTRIDE + c1] = ra1;
        *(uint4*)&sB[0][r0 * SSTRIDE + c0] = rb0;
        *(uint4*)&sB[0][r1 * SSTRIDE + c1] = rb1;
    }
    __syncthreads();

    for (int kt = 0; kt < KTILES; kt++) {
        int buf = kt & 1;
        if (kt + 1 < KTILES) {
            int k0 = (kt + 1) * 32;
            ra0 = *(const uint4*)&g_xa[(size_t)(rowBase + r0) * KPAD + k0 + c0];
            ra1 = *(const uint4*)&g_xa[(size_t)(rowBase + r1) * KPAD + k0 + c1];
            rb0 = *(const uint4*)&g_wb[(size_t)(colBase + r0) * KPAD + k0 + c0];
            rb1 = *(const uint4*)&g_wb[(size_t)(colBase + r1) * KPAD + k0 + c1];
        }
        uint32_t aBase = smem_u32(sA[buf]);
        uint32_t bBase = smem_u32(sB[buf]);
        #pragma unroll
        for (int s = 0; s < 2; s++) {
            uint32_t a[2][4];
            #pragma unroll
            for (int mf = 0; mf < 2; mf++) {
                int row = warpM * 32 + mf * 16 + (lane & 7) + ((lane >> 3) & 1) * 8;
                uint32_t addr = aBase + row * 80 + s * 32 + ((lane >> 4) & 1) * 16;
                ldsm_x4(a[mf][0], a[mf][1], a[mf][2], a[mf][3], addr);
            }
            uint32_t b[8][2];
            #pragma unroll
            for (int nf2 = 0; nf2 < 4; nf2++) {
                int rn = warpN * 64 + nf2 * 16 + (lane & 7) + ((lane >> 4) & 1) * 8;
                uint32_t addr = bBase + rn * 80 + s * 32 + ((lane >> 3) & 1) * 16;
                ldsm_x4(b[nf2 * 2][0], b[nf2 * 2][1], b[nf2 * 2 + 1][0], b[nf2 * 2 + 1][1], addr);
            }
            #pragma unroll
            for (int mf = 0; mf < 2; mf++)
                #pragma unroll
                for (int nf = 0; nf < 8; nf++)
                    mma16816(acc[mf][nf], a[mf][0], a[mf][1], a[mf][2], a[mf][3],
                             b[nf][0], b[nf][1]);
        }
        if (kt + 1 < KTILES) {
            int nb = buf ^ 1;
            *(uint4*)&sA[nb][r0 * SSTRIDE + c0] = ra0;
            *(uint4*)&sA[nb][r1 * SSTRIDE + c1] = ra1;
            *(uint4*)&sB[nb][r0 * SSTRIDE + c0] = rb0;
            *(uint4*)&sB[nb][r1 * SSTRIDE + c1] = rb1;
        }
        __syncthreads();
    }

    // Epilogue: bias + target-noise, scalar stores (NTOKEN odd -> rows misaligned),
    // plus per-row partial (max, sumexp) over this tile's 128 columns.
    int groupRow = lane >> 2;
    int colPair  = (lane & 3) * 2;
    #pragma unroll
    for (int mf = 0; mf < 2; mf++) {
        #pragma unroll
        for (int half = 0; half < 2; half++) {
            int rl = warpM * 32 + mf * 16 + groupRow + half * 8;
            int gr = rowBase + rl;
            if (gr >= NROWS) continue;           // warp-uniform (boundary at warpM)
            int t = s_tgt[rl];
            float nz = s_noise[rl];
            size_t ob = (size_t)gr * NTOKEN;
            float vv[16];
            float lm = -1e30f;
            #pragma unroll
            for (int nf = 0; nf < 8; nf++) {
                int cl = warpN * 64 + nf * 8 + colPair;
                int gc = colBase + cl;
                float v0 = acc[mf][nf][half * 2 + 0] + s_bias[cl];
                float v1 = acc[mf][nf][half * 2 + 1] + s_bias[cl + 1];
                if (gc == t)     v0 += nz;
                if (gc + 1 == t) v1 += nz;
                bool ok0 = gc < NTOKEN, ok1 = gc + 1 < NTOKEN;
                if (ok0) out[ob + gc]     = v0;
                if (ok1) out[ob + gc + 1] = v1;
                vv[nf * 2]     = ok0 ? v0 : -1e30f;
                vv[nf * 2 + 1] = ok1 ? v1 : -1e30f;
                lm = fmaxf(lm, fmaxf(vv[nf * 2], vv[nf * 2 + 1]));
            }
            float ls = 0.f;
            #pragma unroll
            for (int q = 0; q < 16; q++) ls += __expf(vv[q] - lm);
            // merge across the quad sharing this row (lanes 4g..4g+3)
            #pragma unroll
            for (int o = 1; o <= 2; o <<= 1) {
                float om = __shfl_xor_sync(0xffffffffu, lm, o);
                float os = __shfl_xor_sync(0xffffffffu, ls, o);
                float nm = fmaxf(lm, om);
                ls = ls * __expf(lm - nm) + os * __expf(om - nm);
                lm = nm;
            }
            if ((lane & 3) == 0) { sm_m[warpN][rl] = lm; sm_s[warpN][rl] = ls; }
        }
    }
    __syncthreads();
    if (tid < 128) {
        int gr = rowBase + tid;
        if (gr < NROWS) {
            float m0 = sm_m[0][tid], s0 = sm_s[0][tid];
            float m1 = sm_m[1][tid], s1 = sm_s[1][tid];
            float mm = fmaxf(m0, m1);
            float ssum = s0 * __expf(m0 - mm) + s1 * __expf(m1 - mm);
            g_pm[(size_t)gr * NTILES + blockIdx.x] = mm;
            g_ps[(size_t)gr * NTILES + blockIdx.x] = ssum;
        }
    }
}

// ---------------- finalize: reduce 393 partials per row -> lse ----------------
__global__ void k_fin() {
    int row = blockIdx.x;
    const float* pm = &g_pm[(size_t)row * NTILES];
    const float* ps = &g_ps[(size_t)row * NTILES];
    float m = -1e30f, s = 0.f;
    for (int i = threadIdx.x; i < NTILES; i += blockDim.x) {
        float tm = pm[i], ts = ps[i];
        float nm = fmaxf(m, tm);
        s = s * __expf(m - nm) + ts * __expf(tm - nm);
        m = nm;
    }
    int lane = threadIdx.x & 31, w = threadIdx.x >> 5;
    #pragma unroll
    for (int o = 16; o; o >>= 1) {
        float om = __shfl_xor_sync(0xffffffffu, m, o);
        float os = __shfl_xor_sync(0xffffffffu, s, o);
        float nm = fmaxf(m, om);
        s = s * __expf(m - nm) + os * __expf(om - nm);
        m = nm;
    }
    __shared__ float shm[4], shs[4];
    if (lane == 0) { shm[w] = m; shs[w] = s; }
    __syncthreads();
    if (threadIdx.x == 0) {
        m = shm[0]; s = shs[0];
        #pragma unroll
        for (int i = 1; i < 4; i++) {
            float nm = fmaxf(m, shm[i]);
            s = s * __expf(m - nm) + shs[i] * __expf(shm[i] - nm);
            m = nm;
        }
        g_lse[row] = m + __logf(s);
    }
}

// ---------------- subtract pass (alignment-safe: NTOKEN odd) ----------------
__global__ void k_sub(float* __restrict__ out) {
    int row = blockIdx.x;
    float l = g_lse[row];
    float* p = out + (size_t)row * NTOKEN;
    int head = (int)(((16u - ((uint32_t)(uintptr_t)p & 15u)) & 15u) >> 2);
    int n4 = (NTOKEN - head) >> 2;
    int tail = NTOKEN - head - n4 * 4;

    if (threadIdx.x < (unsigned)head) p[threadIdx.x] -= l;
    float4* p4 = (float4*)(p + head);
    for (int i = threadIdx.x; i < n4; i += blockDim.x) {
        float4 v = p4[i];
        v.x -= l; v.y -= l; v.z -= l; v.w -= l;
        p4[i] = v;
    }
    if (threadIdx.x < (unsigned)tail) p[head + n4 * 4 + threadIdx.x] -= l;
}

// ---------------- launch ----------------
extern "C" void kernel_launch(void* const* d_in, const int* in_sizes, int n_in,
                              void* d_out, int out_size) {
    const float* x     = (const float*)d_in[0];
    const float* dec_w = (const float*)d_in[1];
    const float* dec_b = (const float*)d_in[2];
    const float* enc_w = (const float*)d_in[3];
    const int*   tgt   = (const int*)d_in[4];
    float* out = (float*)d_out;

    long long xg = (long long)MPAD * (KPAD / 8);
    long long wg = (long long)NPAD * (KPAD / 8);
    k_cvt_x<<<(unsigned)((xg + 255) / 256), 256>>>(x);
    k_cvt_w<<<(unsigned)((wg + 255) / 256), 256>>>(dec_w);

    k_init_last<<<(NROWS + 255) / 256, 256>>>(tgt);
    k_row_stats<<<NROWS, 128>>>(x, enc_w, tgt);
    k_noise<<<NROWS, 128>>>(x, tgt);

    dim3 grid(NPAD / 128, MPAD / 128);
    k_gemm_tc<<<grid, 256>>>(dec_b, tgt, out);

    k_fin<<<NROWS, 128>>>();
    k_sub<<<NROWS, 1024>>>(out);
}

// round 7
// speedup vs baseline: 4.2162x; 1.0331x over previous
#include <cuda_runtime.h>
#include <cuda_bf16.h>
#include <stdint.h>
#include <math.h>

#define NTOKEN 50257
#define NROWS  2240
#define DIM    400
#define KPAD   416              // 13 * 32
#define MPAD   2304             // 18 * 128
#define NPAD   50304            // 393 * 128
#define KTILES 13
#define NTILES (NPAD / 128)     // 393 col-tiles
#define SSTRIDE 40              // bf16 per smem row (80B) -> conflict-free ldmatrix

#define XGRP ((long long)MPAD * (KPAD / 8))          // 119808
#define WGRP ((long long)NPAD * (KPAD / 8))          // 2615808
#define WBLK ((int)((WGRP + 255) / 256))             // cvt_w blocks in k_pro_b

// ---------------- device scratch ----------------
__device__ int   g_last[NTOKEN];
__device__ float g_sfac[NROWS];
__device__ float g_noise[NROWS];
__device__ float g_pm[(size_t)NROWS * NTILES];
__device__ float g_ps[(size_t)NROWS * NTILES];
__device__ __nv_bfloat16 g_xa[(size_t)MPAD * KPAD];
__device__ __nv_bfloat16 g_wb[(size_t)NPAD * KPAD];

// ---------------- helpers ----------------
__device__ __forceinline__ uint32_t smem_u32(const void* p) {
    uint32_t a;
    asm("{ .reg .u64 t; cvta.to.shared.u64 t, %1; cvt.u32.u64 %0, t; }" : "=r"(a) : "l"(p));
    return a;
}
__device__ __forceinline__ void ldsm_x4(uint32_t& r0, uint32_t& r1, uint32_t& r2, uint32_t& r3,
                                        uint32_t addr) {
    asm volatile("ldmatrix.sync.aligned.m8n8.x4.shared.b16 {%0,%1,%2,%3}, [%4];"
                 : "=r"(r0), "=r"(r1), "=r"(r2), "=r"(r3) : "r"(addr));
}
__device__ __forceinline__ void mma16816(float* c, uint32_t a0, uint32_t a1, uint32_t a2,
                                         uint32_t a3, uint32_t b0, uint32_t b1) {
    asm volatile("mma.sync.aligned.m16n8k16.row.col.f32.bf16.bf16.f32 "
                 "{%0,%1,%2,%3}, {%4,%5,%6,%7}, {%8,%9}, {%0,%1,%2,%3};"
                 : "+f"(c[0]), "+f"(c[1]), "+f"(c[2]), "+f"(c[3])
                 : "r"(a0), "r"(a1), "r"(a2), "r"(a3), "r"(b0), "r"(b1));
}
__device__ __forceinline__ void cp16(uint32_t dst, const void* src) {
    asm volatile("cp.async.cg.shared.global [%0], [%1], 16;" :: "r"(dst), "l"(src));
}
#define CP_COMMIT() asm volatile("cp.async.commit_group;" ::: "memory")
#define CP_WAIT0()  asm volatile("cp.async.wait_group 0;" ::: "memory")

__device__ __forceinline__ float warp_sum(float v) {
    #pragma unroll
    for (int o = 16; o; o >>= 1) v += __shfl_down_sync(0xffffffffu, v, o);
    return v;
}

// ---------------- fp32 -> padded bf16 conversion body ----------------
__device__ __forceinline__ void cvt_one(const float* __restrict__ src,
                                        __nv_bfloat16* __restrict__ dst,
                                        int srows, long long i) {
    int row = (int)(i / (KPAD / 8));
    int g   = (int)(i % (KPAD / 8));
    __align__(16) __nv_bfloat16 v[8];
    if (row < srows && g * 8 < DIM) {
        const float* s = src + (long long)row * DIM + g * 8;
        #pragma unroll
        for (int j = 0; j < 8; j++) v[j] = __float2bfloat16(s[j]);
    } else {
        #pragma unroll
        for (int j = 0; j < 8; j++) v[j] = __float2bfloat16(0.f);
    }
    *reinterpret_cast<uint4*>(dst + (size_t)row * KPAD + g * 8) =
        *reinterpret_cast<const uint4*>(v);
}

// ---------------- launch 1: cvt_x + init_last ----------------
__global__ void k_pro_a(const float* __restrict__ x, const int* __restrict__ tgt) {
    long long i = (long long)blockIdx.x * blockDim.x + threadIdx.x;
    if (i < NROWS) g_last[tgt[i]] = -1;
    if (i < XGRP) cvt_one(x, g_xa, NROWS, i);
}

// ---------------- launch 2: cvt_w + row_stats (block-partitioned) ----------------
__global__ void k_pro_b(const float* __restrict__ dec_w,
                        const float* __restrict__ x,
                        const float* __restrict__ enc_w,
                        const int* __restrict__ tgt) {
    if (blockIdx.x < WBLK) {
        long long i = (long long)blockIdx.x * blockDim.x + threadIdx.x;
        if (i < WGRP) cvt_one(dec_w, g_wb, NTOKEN, i);
        return;
    }
    // row_stats: one block (256 threads) per row
    int row = blockIdx.x - WBLK;
    int t = tgt[row];
    const float* hr = x + (long long)row * DIM;
    const float* wr = enc_w + (long long)t * DIM;
    float hsq = 0.f, dhw = 0.f, wsq = 0.f;
    for (int k = threadIdx.x; k < DIM; k += blockDim.x) {
        float hv = hr[k], wv = wr[k];
        hsq += hv * hv; dhw += hv * wv; wsq += wv * wv;
    }
    __shared__ float sh[3][8];
    int lane = threadIdx.x & 31, w = threadIdx.x >> 5;
    hsq = warp_sum(hsq); dhw = warp_sum(dhw); wsq = warp_sum(wsq);
    if (lane == 0) { sh[0][w] = hsq; sh[1][w] = dhw; sh[2][w] = wsq; }
    __syncthreads();
    if (threadIdx.x == 0) {
        hsq = 0.f; dhw = 0.f; wsq = 0.f;
        #pragma unroll
        for (int i = 0; i < 8; i++) { hsq += sh[0][i]; dhw += sh[1][i]; wsq += sh[2][i]; }
        float n_out = sqrtf(hsq + 1e-8f);
        float n_w   = sqrtf(wsq + 1e-8f);
        float cosv  = dhw / (n_out * n_w);
        float eps   = (cosv > 0.f) ? 0.2f * n_w : 0.f;
        g_sfac[row] = -eps / n_out;
        atomicMax(&g_last[t], row);
    }
}

// ---------------- launch 3: noise dot products ----------------
__global__ void k_noise(const float* __restrict__ h, const int* __restrict__ tgt) {
    int row = blockIdx.x;
    int j = g_last[tgt[row]];
    const float* hi = h + (long long)row * DIM;
    const float* hj = h + (long long)j * DIM;
    float d = 0.f;
    for (int k = threadIdx.x; k < DIM; k += blockDim.x) d += hi[k] * hj[k];
    __shared__ float sh[4];
    d = warp_sum(d);
    if ((threadIdx.x & 31) == 0) sh[threadIdx.x >> 5] = d;
    __syncthreads();
    if (threadIdx.x == 0)
        g_noise[row] = g_sfac[j] * (sh[0] + sh[1] + sh[2] + sh[3]);
}

// ---------------- launch 4: HMMA bf16 GEMM, cp.async 2-stage pipeline ----------------
__global__ void __launch_bounds__(256, 2) k_gemm_tc(
    const float* __restrict__ bias, const int* __restrict__ tgt,
    float* __restrict__ out)
{
    __shared__ __align__(16) __nv_bfloat16 sA[2][128 * SSTRIDE];
    __shared__ __align__(16) __nv_bfloat16 sB[2][128 * SSTRIDE];
    __shared__ int   s_tgt[128];
    __shared__ float s_noise[128];
    __shared__ float s_bias[128];
    __shared__ float sm_m[2][128];
    __shared__ float sm_s[2][128];

    int tid = threadIdx.x, lane = tid & 31, wid = tid >> 5;
    int warpM = wid & 3, warpN = wid >> 2;
    int rowBase = blockIdx.y * 128, colBase = blockIdx.x * 128;

    if (tid < 128) {
        int gr = rowBase + tid;
        s_tgt[tid]   = (gr < NROWS) ? tgt[gr]     : -1;
        s_noise[tid] = (gr < NROWS) ? g_noise[gr] : 0.f;
        int gc = colBase + tid;
        s_bias[tid]  = (gc < NTOKEN) ? bias[gc]   : 0.f;
    }

    // per-thread global<->smem chunk mapping (512 16B chunks per matrix tile)
    int i0 = tid, i1 = tid + 256;
    int r0 = i0 >> 2, c0 = (i0 & 3) * 8;
    int r1 = i1 >> 2, c1 = (i1 & 3) * 8;
    const __nv_bfloat16* gA0 = &g_xa[(size_t)(rowBase + r0) * KPAD + c0];
    const __nv_bfloat16* gA1 = &g_xa[(size_t)(rowBase + r1) * KPAD + c1];
    const __nv_bfloat16* gB0 = &g_wb[(size_t)(colBase + r0) * KPAD + c0];
    const __nv_bfloat16* gB1 = &g_wb[(size_t)(colBase + r1) * KPAD + c1];
    uint32_t sA0[2], sA1[2], sB0[2], sB1[2];
    #pragma unroll
    for (int b = 0; b < 2; b++) {
        sA0[b] = smem_u32(&sA[b][r0 * SSTRIDE + c0]);
        sA1[b] = smem_u32(&sA[b][r1 * SSTRIDE + c1]);
        sB0[b] = smem_u32(&sB[b][r0 * SSTRIDE + c0]);
        sB1[b] = smem_u32(&sB[b][r1 * SSTRIDE + c1]);
    }

    float acc[2][8][4];
    #pragma unroll
    for (int m = 0; m < 2; m++)
        #pragma unroll
        for (int n = 0; n < 8; n++)
            #pragma unroll
            for (int j = 0; j < 4; j++) acc[m][n][j] = 0.f;

    // preload k-tile 0 into buffer 0
    cp16(sA0[0], gA0); cp16(sA1[0], gA1);
    cp16(sB0[0], gB0); cp16(sB1[0], gB1);
    CP_COMMIT();

    uint32_t aWarpBase0 = smem_u32(sA[0]), bWarpBase0 = smem_u32(sB[0]);
    uint32_t bufBytes = 128 * SSTRIDE * 2;

    for (int kt = 0; kt < KTILES; kt++) {
        int buf = kt & 1;
        CP_WAIT0();
        __syncthreads();
        if (kt + 1 < KTILES) {
            int k0 = (kt + 1) * 32, nb = buf ^ 1;
            cp16(sA0[nb], gA0 + k0); cp16(sA1[nb], gA1 + k0);
            cp16(sB0[nb], gB0 + k0); cp16(sB1[nb], gB1 + k0);
            CP_COMMIT();
        }
        uint32_t aBase = aWarpBase0 + buf * bufBytes;
        uint32_t bBase = bWarpBase0 + buf * bufBytes;
        #pragma unroll
        for (int s = 0; s < 2; s++) {
            uint32_t a[2][4];
            #pragma unroll
            for (int mf = 0; mf < 2; mf++) {
                int row = warpM * 32 + mf * 16 + (lane & 7) + ((lane >> 3) & 1) * 8;
                uint32_t addr = aBase + row * 80 + s * 32 + ((lane >> 4) & 1) * 16;
                ldsm_x4(a[mf][0], a[mf][1], a[mf][2], a[mf][3], addr);
            }
            uint32_t b[8][2];
            #pragma unroll
            for (int nf2 = 0; nf2 < 4; nf2++) {
                int rn = warpN * 64 + nf2 * 16 + (lane & 7) + ((lane >> 4) & 1) * 8;
                uint32_t addr = bBase + rn * 80 + s * 32 + ((lane >> 3) & 1) * 16;
                ldsm_x4(b[nf2 * 2][0], b[nf2 * 2][1], b[nf2 * 2 + 1][0], b[nf2 * 2 + 1][1], addr);
            }
            #pragma unroll
            for (int mf = 0; mf < 2; mf++)
                #pragma unroll
                for (int nf = 0; nf < 8; nf++)
                    mma16816(acc[mf][nf], a[mf][0], a[mf][1], a[mf][2], a[mf][3],
                             b[nf][0], b[nf][1]);
        }
    }
    __syncthreads();

    // Epilogue: bias + target-noise (scalar stores: NTOKEN odd => rows misaligned),
    // plus per-row partial (max, sumexp) over this tile's 128 columns.
    int groupRow = lane >> 2;
    int colPair  = (lane & 3) * 2;
    #pragma unroll
    for (int mf = 0; mf < 2; mf++) {
        #pragma unroll
        for (int half = 0; half < 2; half++) {
            int rl = warpM * 32 + mf * 16 + groupRow + half * 8;
            int gr = rowBase + rl;
            if (gr >= NROWS) continue;           // warp-uniform (NROWS % 32 == 0)
            int t = s_tgt[rl];
            float nz = s_noise[rl];
            size_t ob = (size_t)gr * NTOKEN;
            float vv[16];
            float lm = -1e30f;
            #pragma unroll
            for (int nf = 0; nf < 8; nf++) {
                int cl = warpN * 64 + nf * 8 + colPair;
                int gc = colBase + cl;
                float v0 = acc[mf][nf][half * 2 + 0] + s_bias[cl];
                float v1 = acc[mf][nf][half * 2 + 1] + s_bias[cl + 1];
                if (gc == t)     v0 += nz;
                if (gc + 1 == t) v1 += nz;
                bool ok0 = gc < NTOKEN, ok1 = gc + 1 < NTOKEN;
                if (ok0) out[ob + gc]     = v0;
                if (ok1) out[ob + gc + 1] = v1;
                vv[nf * 2]     = ok0 ? v0 : -1e30f;
                vv[nf * 2 + 1] = ok1 ? v1 : -1e30f;
                lm = fmaxf(lm, fmaxf(vv[nf * 2], vv[nf * 2 + 1]));
            }
            float ls = 0.f;
            #pragma unroll
            for (int q = 0; q < 16; q++) ls += __expf(vv[q] - lm);
            #pragma unroll
            for (int o = 1; o <= 2; o <<= 1) {
                float om = __shfl_xor_sync(0xffffffffu, lm, o);
                float os = __shfl_xor_sync(0xffffffffu, ls, o);
                float nm = fmaxf(lm, om);
                ls = ls * __expf(lm - nm) + os * __expf(om - nm);
                lm = nm;
            }
            if ((lane & 3) == 0) { sm_m[warpN][rl] = lm; sm_s[warpN][rl] = ls; }
        }
    }
    __syncthreads();
    if (tid < 128) {
        int gr = rowBase + tid;
        if (gr < NROWS) {
            float m0 = sm_m[0][tid], s0 = sm_s[0][tid];
            float m1 = sm_m[1][tid], s1 = sm_s[1][tid];
            float mm = fmaxf(m0, m1);
            float ssum = s0 * __expf(m0 - mm) + s1 * __expf(m1 - mm);
            g_pm[(size_t)gr * NTILES + blockIdx.x] = mm;
            g_ps[(size_t)gr * NTILES + blockIdx.x] = ssum;
        }
    }
}

// ---------------- launch 5: finalize lse + subtract (fused) ----------------
__global__ void k_subfin(float* __restrict__ out) {
    int row = blockIdx.x;
    // 1) reduce NTILES partials -> lse
    const float* pm = &g_pm[(size_t)row * NTILES];
    const float* ps = &g_ps[(size_t)row * NTILES];
    float m = -1e30f, s = 0.f;
    for (int i = threadIdx.x; i < NTILES; i += blockDim.x) {
        float tm = pm[i], ts = ps[i];
        float nm = fmaxf(m, tm);
        s = s * __expf(m - nm) + ts * __expf(tm - nm);
        m = nm;
    }
    int lane = threadIdx.x & 31, w = threadIdx.x >> 5;
    #pragma unroll
    for (int o = 16; o; o >>= 1) {
        float om = __shfl_xor_sync(0xffffffffu, m, o);
        float os = __shfl_xor_sync(0xffffffffu, s, o);
        float nm = fmaxf(m, om);
        s = s * __expf(m - nm) + os * __expf(om - nm);
        m = nm;
    }
    __shared__ float shm[32], shs[32];
    __shared__ float sh_l;
    if (lane == 0) { shm[w] = m; shs[w] = s; }
    __syncthreads();
    if (threadIdx.x == 0) {
        int nw = (int)(blockDim.x >> 5);
        m = shm[0]; s = shs[0];
        for (int i = 1; i < nw; i++) {
            float nm = fmaxf(m, shm[i]);
            s = s * __expf(m - nm) + shs[i] * __expf(shm[i] - nm);
            m = nm;
        }
        sh_l = m + __logf(s);
    }
    __syncthreads();
    float l = sh_l;

    // 2) subtract (alignment-safe: NTOKEN odd)
    float* p = out + (size_t)row * NTOKEN;
    int head = (int)(((16u - ((uint32_t)(uintptr_t)p & 15u)) & 15u) >> 2);
    int n4 = (NTOKEN - head) >> 2;
    int tail = NTOKEN - head - n4 * 4;
    if (threadIdx.x < (unsigned)head) p[threadIdx.x] -= l;
    float4* p4 = (float4*)(p + head);
    for (int i = threadIdx.x; i < n4; i += blockDim.x) {
        float4 v = p4[i];
        v.x -= l; v.y -= l; v.z -= l; v.w -= l;
        p4[i] = v;
    }
    if (threadIdx.x < (unsigned)tail) p[head + n4 * 4 + threadIdx.x] -= l;
}

// ---------------- launch ----------------
extern "C" void kernel_launch(void* const* d_in, const int* in_sizes, int n_in,
                              void* d_out, int out_size) {
    const float* x     = (const float*)d_in[0];
    const float* dec_w = (const float*)d_in[1];
    const float* dec_b = (const float*)d_in[2];
    const float* enc_w = (const float*)d_in[3];
    const int*   tgt   = (const int*)d_in[4];
    float* out = (float*)d_out;

    k_pro_a<<<(unsigned)((XGRP + 255) / 256), 256>>>(x, tgt);            // 1
    k_pro_b<<<(unsigned)(WBLK + NROWS), 256>>>(dec_w, x, enc_w, tgt);    // 2
    k_noise<<<NROWS, 128>>>(x, tgt);                                     // 3
    dim3 grid(NPAD / 128, MPAD / 128);
    k_gemm_tc<<<grid, 256>>>(dec_b, tgt, out);                           // 4 (profiled)
    k_subfin<<<NROWS, 1024>>>(out);                                      // 5
}